// round 17
// baseline (speedup 1.0000x reference)
#include <cuda_runtime.h>
#include <cuda_bf16.h>
#include <math.h>
#include <cstdint>

#define NB 128
#define NQ 30
#define ND 256
#define NE 300
#define KP 320
#define XQROWS 34
#define XDROWS 258

// ---------------- scratch ----------------
__device__ __align__(16) __nv_bfloat16 g_Xqh[NB * XQROWS * KP];
__device__ __align__(16) __nv_bfloat16 g_Xql[NB * XQROWS * KP];
__device__ __align__(16) __nv_bfloat16 g_Xdh[NB * XDROWS * KP];
__device__ __align__(16) __nv_bfloat16 g_Xdl[NB * XDROWS * KP];
__device__ __align__(16) __nv_bfloat16 g_Wh[245760];
__device__ __align__(16) __nv_bfloat16 g_Wl[245760];
__device__ __align__(16) __nv_bfloat16 g_Qh2[NB * 32 * 384];   // rows 30,31 stay zero
__device__ __align__(16) __nv_bfloat16 g_Ql2[NB * 32 * 384];
__device__ __align__(16) __nv_bfloat16 g_Dh2[NB * ND * 384];
__device__ __align__(16) __nv_bfloat16 g_Dl2[NB * ND * 384];
__device__ float g_pk[NB * 9 * 30 * 11];
__device__ float g_feat[NB * 99];

__device__ __forceinline__ uint32_t smem_u32(const void* p) {
    uint32_t a;
    asm("{ .reg .u64 t; cvta.to.shared.u64 t, %1; cvt.u32.u64 %0, t; }" : "=r"(a) : "l"(p));
    return a;
}
__device__ __forceinline__ void ldsm4(uint32_t* r, uint32_t addr) {
    asm volatile("ldmatrix.sync.aligned.m8n8.x4.shared.b16 {%0,%1,%2,%3}, [%4];"
                 : "=r"(r[0]), "=r"(r[1]), "=r"(r[2]), "=r"(r[3]) : "r"(addr));
}
__device__ __forceinline__ void mma16816(float* c, const uint32_t* a, const uint32_t* b) {
    asm volatile("mma.sync.aligned.m16n8k16.row.col.f32.bf16.bf16.f32 "
                 "{%0,%1,%2,%3}, {%4,%5,%6,%7}, {%8,%9}, {%0,%1,%2,%3};"
                 : "+f"(c[0]), "+f"(c[1]), "+f"(c[2]), "+f"(c[3])
                 : "r"(a[0]), "r"(a[1]), "r"(a[2]), "r"(a[3]), "r"(b[0]), "r"(b[1]));
}
__device__ __forceinline__ void cpa16(uint32_t dst, const void* src) {
    asm volatile("cp.async.cg.shared.global [%0], [%1], 16;" :: "r"(dst), "l"(src) : "memory");
}
#define CP_COMMIT() asm volatile("cp.async.commit_group;" ::: "memory")
#define CP_WAIT(n)  asm volatile("cp.async.wait_group %0;" :: "n"(n) : "memory")

// ---------------- prep kernels (proven) ----------------
__global__ __launch_bounds__(256) void prep_w(const float* __restrict__ w1,
                                              const float* __restrict__ w2,
                                              const float* __restrict__ w3)
{
    int idx = blockIdx.x * 256 + threadIdx.x;
    if (idx >= 245760) return;
    int g, base, rs;
    if (idx < 40960)       { g = 0; base = 0;      rs = 320; }
    else if (idx < 122880) { g = 1; base = 40960;  rs = 640; }
    else                   { g = 2; base = 122880; rs = 960; }
    int off = idx - base;
    int n = off / rs;
    int r = off - n * rs;
    int tap = r / KP;
    int e = r - tap * KP;
    float v = 0.f;
    if (e < NE) {
        const float* w = (g == 0) ? w1 : ((g == 1) ? w2 : w3);
        v = w[(n * NE + e) * (g + 1) + tap];
    }
    __nv_bfloat16 h = __float2bfloat16(v);
    g_Wh[idx] = h;
    g_Wl[idx] = __float2bfloat16(v - __bfloat162float(h));
}

template<int ROWS, int LVALID>
__global__ __launch_bounds__(256) void prep_x(const float* __restrict__ X,
                                              __nv_bfloat16* __restrict__ Xh,
                                              __nv_bfloat16* __restrict__ Xl)
{
    int idx = blockIdx.x * 256 + threadIdx.x;
    const int T = NB * ROWS * (KP / 4);
    if (idx >= T) return;
    int e4  = idx % (KP / 4);
    int row = idx / (KP / 4);
    int b = row / ROWS;
    int p = row - b * ROWS;
    int e0 = e4 * 4;
    float4 v = make_float4(0.f, 0.f, 0.f, 0.f);
    if (p < LVALID && e0 < NE)
        v = *(const float4*)&X[((size_t)(b * LVALID + p)) * NE + e0];
    __nv_bfloat16 h[4], l[4];
    float vv[4] = {v.x, v.y, v.z, v.w};
#pragma unroll
    for (int j = 0; j < 4; j++) {
        h[j] = __float2bfloat16(vv[j]);
        l[j] = __float2bfloat16(vv[j] - __bfloat162float(h[j]));
    }
    size_t o = (size_t)row * KP + e0;
    *(__nv_bfloat162*)&Xh[o]     = *(__nv_bfloat162*)&h[0];
    *(__nv_bfloat162*)&Xh[o + 2] = *(__nv_bfloat162*)&h[2];
    *(__nv_bfloat162*)&Xl[o]     = *(__nv_bfloat162*)&l[0];
    *(__nv_bfloat162*)&Xl[o + 2] = *(__nv_bfloat162*)&l[2];
}

// ---------------- merged conv GEMM (round-13 proven; sole delta: .cg) ----------------
#define S_AH 0
#define S_AL 10240
#define S_BH 20480
#define S_BL 30720
#define C_STG 40960
#define C_SQ  (2 * C_STG)
#define C_TOT (C_SQ + 512)

__global__ __launch_bounds__(256, 2) void convmma(const float* __restrict__ bs0,
                                                  const float* __restrict__ bs1,
                                                  const float* __restrict__ bs2)
{
    constexpr int NFRAG = 8, NJ2 = 4, SA = 40;

    extern __shared__ char sm[];
    const uint32_t sbase = smem_u32(sm);

    const int tid  = threadIdx.x;
    const int wid  = tid >> 5;
    const int lane = tid & 31;
    const int wr  = wid >> 1;
    const int wcn = wid & 1;
    const int mr = wr * 32;
    const int nc = wcn * 64;

    const int bidx = blockIdx.x;
    const int g   = (bidx < 288) ? 2 : ((bidx < 576) ? 1 : 0);
    const int sub = bidx - ((g == 2) ? 0 : ((g == 1) ? 288 : 576));
    const bool isq = (sub >= 256);
    const int m0 = isq ? 0 : ((sub & 1) * 128);
    const int b0 = isq ? (sub - 256) * 4 : (sub >> 1);

    const int wbase = (g == 0) ? 0 : ((g == 1) ? 40960 : 122880);
    const int wrs = (g + 1) * KP;
    const float* bias = (g == 0) ? bs0 : ((g == 1) ? bs1 : bs2);
    const __nv_bfloat16* Xh = isq ? g_Xqh : g_Xdh;
    const __nv_bfloat16* Xl = isq ? g_Xql : g_Xdl;
    const int XR = isq ? XQROWS : XDROWS;

    if (tid < 128) *(float*)(sm + C_SQ + tid * 4) = 0.f;

    const int lg = lane >> 3, l7 = lane & 7;
    const uint32_t a_off = ((mr + (lg & 1) * 8 + l7) * SA + ((lg >> 1) * 8)) * 2;
    const uint32_t b_off = ((nc + (lg >> 1) * 8 + l7) * SA + ((lg & 1) * 8)) * 2;

    float acc[2][NFRAG][4];
#pragma unroll
    for (int f = 0; f < 2; f++)
#pragma unroll
        for (int j = 0; j < NFRAG; j++)
#pragma unroll
            for (int t = 0; t < 4; t++) acc[f][j][t] = 0.f;

    const int NCC = 10 * (g + 1);

    auto load_stage = [&](int s) {
        uint32_t sb = sbase + (uint32_t)(s & 1) * C_STG;
        int tap = s / 10;
        int e0 = (s - tap * 10) * 32;
        const __nv_bfloat16* bh = g_Wh + wbase + tap * KP + e0;
        const __nv_bfloat16* bl = g_Wl + wbase + tap * KP + e0;
#pragma unroll
        for (int it = 0; it < 2; it++) {
            int u = tid + it * 256;
            int r = u >> 2, c = u & 3;
            size_t arow = isq ? ((size_t)(b0 + (r >> 5)) * XR + (r & 31) + tap)
                              : ((size_t)b0 * XR + m0 + r + tap);
            size_t go = arow * KP + e0 + c * 8;
            uint32_t dof = r * 80 + c * 16;
            cpa16(sb + S_AH + dof, Xh + go);
            cpa16(sb + S_AL + dof, Xl + go);
            cpa16(sb + S_BH + dof, bh + (size_t)r * wrs + c * 8);
            cpa16(sb + S_BL + dof, bl + (size_t)r * wrs + c * 8);
        }
    };

    load_stage(0);
    CP_COMMIT();

    for (int cc = 0; cc < NCC; cc++) {
        if (cc + 1 < NCC) { load_stage(cc + 1); CP_COMMIT(); }
        if (cc + 1 < NCC) CP_WAIT(1); else CP_WAIT(0);
        __syncthreads();

        const uint32_t sb = sbase + (uint32_t)(cc & 1) * C_STG;
#pragma unroll
        for (int ks = 0; ks < 2; ks++) {
            uint32_t ahf[2][4], alf[2][4];
            ldsm4(ahf[0], sb + S_AH + a_off + ks * 32);
            ldsm4(ahf[1], sb + S_AH + a_off + 16 * SA * 2 + ks * 32);
            ldsm4(alf[0], sb + S_AL + a_off + ks * 32);
            ldsm4(alf[1], sb + S_AL + a_off + 16 * SA * 2 + ks * 32);
            {
                uint32_t bf[NJ2][4];
#pragma unroll
                for (int j2 = 0; j2 < NJ2; j2++)
                    ldsm4(bf[j2], sb + S_BH + b_off + j2 * 16 * SA * 2 + ks * 32);
#pragma unroll
                for (int f = 0; f < 2; f++)
#pragma unroll
                    for (int j = 0; j < NFRAG; j++) {
                        const uint32_t* bp = &bf[j >> 1][(j & 1) * 2];
                        mma16816(acc[f][j], ahf[f], bp);
                        mma16816(acc[f][j], alf[f], bp);
                    }
            }
            {
                uint32_t bf[NJ2][4];
#pragma unroll
                for (int j2 = 0; j2 < NJ2; j2++)
                    ldsm4(bf[j2], sb + S_BL + b_off + j2 * 16 * SA * 2 + ks * 32);
#pragma unroll
                for (int f = 0; f < 2; f++)
#pragma unroll
                    for (int j = 0; j < NFRAG; j++) {
                        const uint32_t* bp = &bf[j >> 1][(j & 1) * 2];
                        mma16816(acc[f][j], ahf[f], bp);
                    }
            }
        }
        __syncthreads();
    }

    const int lq = lane >> 2, lr = lane & 3;
    float ssq_p[2][2] = {{0.f, 0.f}, {0.f, 0.f}};
#pragma unroll
    for (int f = 0; f < 2; f++)
#pragma unroll
        for (int j = 0; j < NFRAG; j++) {
            float bv0 = __ldg(&bias[nc + j * 8 + 2 * lr]);
            float bv1 = __ldg(&bias[nc + j * 8 + 2 * lr + 1]);
            float v0 = fmaxf(acc[f][j][0] + bv0, 0.f);
            float v1 = fmaxf(acc[f][j][1] + bv1, 0.f);
            float v2 = fmaxf(acc[f][j][2] + bv0, 0.f);
            float v3 = fmaxf(acc[f][j][3] + bv1, 0.f);
            acc[f][j][0] = v0; acc[f][j][1] = v1; acc[f][j][2] = v2; acc[f][j][3] = v3;
            ssq_p[f][0] += v0 * v0 + v1 * v1;
            ssq_p[f][1] += v2 * v2 + v3 * v3;
        }
#pragma unroll
    for (int f = 0; f < 2; f++)
#pragma unroll
        for (int h = 0; h < 2; h++) {
            float v = ssq_p[f][h];
            v += __shfl_xor_sync(0xffffffffu, v, 1);
            v += __shfl_xor_sync(0xffffffffu, v, 2);
            if (lr == 0)
                atomicAdd((float*)(sm + C_SQ + (mr + f * 16 + h * 8 + lq) * 4), v);
        }
    __syncthreads();

    __nv_bfloat16* OH = isq ? g_Qh2 : g_Dh2;
    __nv_bfloat16* OL = isq ? g_Ql2 : g_Dl2;
#pragma unroll
    for (int f = 0; f < 2; f++)
#pragma unroll
        for (int h = 0; h < 2; h++) {
            int r = mr + f * 16 + h * 8 + lq;
            float inv = 1.f / (sqrtf(*(float*)(sm + C_SQ + r * 4)) + 1e-13f);
            bool valid;
            size_t orow;
            if (isq) {
                int pos = r & 31;
                valid = pos < NQ;
                orow = (size_t)(b0 + (r >> 5)) * 32 + pos;
            } else {
                valid = true;
                orow = (size_t)b0 * ND + m0 + r;
            }
            if (!valid) continue;
            size_t ob = orow * 384 + g * 128;
#pragma unroll
            for (int j = 0; j < NFRAG; j++) {
                float v0 = acc[f][j][h * 2 + 0] * inv;
                float v1 = acc[f][j][h * 2 + 1] * inv;
                __nv_bfloat16 h0 = __float2bfloat16(v0);
                __nv_bfloat16 h1 = __float2bfloat16(v1);
                __nv_bfloat16 l0 = __float2bfloat16(v0 - __bfloat162float(h0));
                __nv_bfloat16 l1 = __float2bfloat16(v1 - __bfloat162float(h1));
                __nv_bfloat162 ph; ph.x = h0; ph.y = h1;
                __nv_bfloat162 pl; pl.x = l0; pl.y = l1;
                size_t o = ob + nc + j * 8 + 2 * lr;
                *(__nv_bfloat162*)&OH[o] = ph;
                *(__nv_bfloat162*)&OL[o] = pl;
            }
        }
}

__global__ __launch_bounds__(256) void zero_pk()
{
    int i = blockIdx.x * 256 + threadIdx.x;
    if (i < NB * 9 * 30 * 11) g_pk[i] = 0.f;
}

// ---------------- pool: proven round-7 kernel (verbatim) ----------------
#define PM_AH 0
#define PM_AL 4608
#define PM_BH 9216
#define PM_BL 27648
#define PM_TOT 46080

__global__ __launch_bounds__(256) void poolmma(const float* __restrict__ qmask,
                                               const float* __restrict__ dmask)
{
    extern __shared__ char sm[];
    const uint32_t sbase = smem_u32(sm);

    const int tid  = threadIdx.x;
    const int wid  = tid >> 5;
    const int lane = tid & 31;
    const int nc = wid * 16;

    const int b    = blockIdx.x;
    const int pair = blockIdx.y;
    const int z    = blockIdx.z;
    const int gi = pair / 3;
    const int gt = pair - gi * 3;

    const int lg = lane >> 3, l7 = lane & 7;
    const uint32_t a_off = (((lg & 1) * 8 + l7) * 72 + ((lg >> 1) * 8)) * 2;
    const uint32_t b_off = ((nc + (lg >> 1) * 8 + l7) * 72 + ((lg & 1) * 8)) * 2;

    float acc[2][2][4];
#pragma unroll
    for (int f = 0; f < 2; f++)
#pragma unroll
        for (int j = 0; j < 2; j++)
#pragma unroll
            for (int t = 0; t < 4; t++) acc[f][j][t] = 0.f;

    for (int cc = 0; cc < 2; cc++) {
        const int e0 = cc * 64;
        const __nv_bfloat16* ah = g_Qh2 + ((size_t)b * 32) * 384 + gi * 128 + e0;
        const __nv_bfloat16* al = g_Ql2 + ((size_t)b * 32) * 384 + gi * 128 + e0;
        const __nv_bfloat16* bh = g_Dh2 + ((size_t)(b * ND + z * 128)) * 384 + gt * 128 + e0;
        const __nv_bfloat16* bl = g_Dl2 + ((size_t)(b * ND + z * 128)) * 384 + gt * 128 + e0;

        __syncthreads();
        {
            int r = tid >> 3, c = tid & 7;
            *(uint4*)(sm + PM_AH + r * 144 + c * 16) = *(const uint4*)(ah + (size_t)r * 384 + c * 8);
            *(uint4*)(sm + PM_AL + r * 144 + c * 16) = *(const uint4*)(al + (size_t)r * 384 + c * 8);
        }
#pragma unroll
        for (int u = tid; u < 1024; u += 256) {
            int r = u >> 3, c = u & 7;
            *(uint4*)(sm + PM_BH + r * 144 + c * 16) = *(const uint4*)(bh + (size_t)r * 384 + c * 8);
            *(uint4*)(sm + PM_BL + r * 144 + c * 16) = *(const uint4*)(bl + (size_t)r * 384 + c * 8);
        }
        __syncthreads();

#pragma unroll
        for (int ks = 0; ks < 4; ks++) {
            uint32_t ahf[2][4], alf[2][4], bhf[4], blf[4];
            ldsm4(ahf[0], sbase + PM_AH + a_off + ks * 32);
            ldsm4(ahf[1], sbase + PM_AH + a_off + 16 * 144 + ks * 32);
            ldsm4(alf[0], sbase + PM_AL + a_off + ks * 32);
            ldsm4(alf[1], sbase + PM_AL + a_off + 16 * 144 + ks * 32);
            ldsm4(bhf, sbase + PM_BH + b_off + ks * 32);
            ldsm4(blf, sbase + PM_BL + b_off + ks * 32);
#pragma unroll
            for (int f = 0; f < 2; f++)
#pragma unroll
                for (int j = 0; j < 2; j++) {
                    mma16816(acc[f][j], ahf[f], &bhf[j * 2]);
                    mma16816(acc[f][j], ahf[f], &blf[j * 2]);
                    mma16816(acc[f][j], alf[f], &bhf[j * 2]);
                }
        }
    }

    const int lq = lane >> 2, lr = lane & 3;
    const float U1 = 0.13533528323661270f;   // e^-2
    const float U2 = 0.018315638888734179f;  // e^-4

    float qacc[4][11];
#pragma unroll
    for (int s = 0; s < 4; s++)
#pragma unroll
        for (int k = 0; k < 11; k++) qacc[s][k] = 0.f;

#pragma unroll
    for (int f = 0; f < 2; f++)
#pragma unroll
        for (int h = 0; h < 2; h++) {
            int row = f * 16 + h * 8 + lq;
            float qmv = (row < NQ) ? __ldg(&qmask[b * NQ + row]) : 0.f;
            int slot = f * 2 + h;
#pragma unroll
            for (int j = 0; j < 2; j++)
#pragma unroll
                for (int e = 0; e < 2; e++) {
                    int col = z * 128 + nc + j * 8 + 2 * lr + e;
                    float m = qmv * __ldg(&dmask[b * ND + col]);
                    float c = acc[f][j][h * 2 + e] * m;
                    float x = c - 0.9f;
                    float e1 = __expf(-50.f * x * x) * m;
                    float t  = __expf(-20.f * x);
                    float t0 = c - 1.0f;
                    qacc[slot][0] += __expf(-500000.f * t0 * t0) * m;
                    float v = e1;
                    qacc[slot][1] += v;
                    float r = t * U1;
#pragma unroll
                    for (int kk = 2; kk < 11; kk++) {
                        v *= r;
                        qacc[slot][kk] += v;
                        r *= U2;
                    }
                }
        }

#pragma unroll
    for (int s = 0; s < 4; s++)
#pragma unroll
        for (int k = 0; k < 11; k++) {
            float v = qacc[s][k];
            v += __shfl_xor_sync(0xffffffffu, v, 1);
            v += __shfl_xor_sync(0xffffffffu, v, 2);
            qacc[s][k] = v;
        }
    if (lr == 0) {
#pragma unroll
        for (int s = 0; s < 4; s++) {
            int row = (s >> 1) * 16 + (s & 1) * 8 + lq;
            if (row < NQ) {
                float* dst = &g_pk[(((size_t)(b * 9 + pair)) * 30 + row) * 11];
#pragma unroll
                for (int k = 0; k < 11; k++) atomicAdd(&dst[k], qacc[s][k]);
            }
        }
    }
}

// ---------------- finish ----------------
__global__ __launch_bounds__(352) void finish_kernel(const float* __restrict__ qmask)
{
    __shared__ float t[330];
    const int b = blockIdx.x, pair = blockIdx.y, tid = threadIdx.x;
    if (tid < 330) {
        int row = tid / 11;
        float pk = fmaxf(g_pk[(((size_t)(b * 9 + pair)) * 30 + row) * 11 + tid % 11], 1e-10f);
        t[tid] = __logf(pk) * 0.01f * __ldg(&qmask[b * NQ + row]);
    }
    __syncthreads();
    if (tid < 11) {
        float s = 0.f;
#pragma unroll
        for (int q = 0; q < NQ; q++) s += t[q * 11 + tid];
        g_feat[b * 99 + pair * 11 + tid] = s;
    }
}

__global__ void final_kernel(const float* __restrict__ dw, float* __restrict__ out)
{
    int b = threadIdx.x;
    if (b < NB) {
        float s = 0.f;
#pragma unroll
        for (int j = 0; j < 99; j++) s += g_feat[b * 99 + j] * dw[j];
        out[b] = s;
    }
}

// ---------------- launch ----------------
extern "C" void kernel_launch(void* const* d_in, const int* in_sizes, int n_in,
                              void* d_out, int out_size)
{
    const float* qe    = (const float*)d_in[0];
    const float* de    = (const float*)d_in[1];
    const float* qmask = (const float*)d_in[2];
    const float* dmask = (const float*)d_in[3];
    const float* w1    = (const float*)d_in[4];
    const float* b1    = (const float*)d_in[5];
    const float* w2    = (const float*)d_in[6];
    const float* b2    = (const float*)d_in[7];
    const float* w3    = (const float*)d_in[8];
    const float* b3    = (const float*)d_in[9];
    const float* dw    = (const float*)d_in[10];
    float* out = (float*)d_out;

    __nv_bfloat16 *xqh, *xql, *xdh, *xdl;
    cudaGetSymbolAddress((void**)&xqh, g_Xqh);
    cudaGetSymbolAddress((void**)&xql, g_Xql);
    cudaGetSymbolAddress((void**)&xdh, g_Xdh);
    cudaGetSymbolAddress((void**)&xdl, g_Xdl);

    prep_w<<<(245760 + 255) / 256, 256>>>(w1, w2, w3);
    prep_x<XQROWS, NQ><<<(NB * XQROWS * (KP / 4) + 255) / 256, 256>>>(qe, xqh, xql);
    prep_x<XDROWS, ND><<<(NB * XDROWS * (KP / 4) + 255) / 256, 256>>>(de, xdh, xdl);

    cudaFuncSetAttribute(convmma, cudaFuncAttributeMaxDynamicSharedMemorySize, C_TOT);
    convmma<<<864, 256, C_TOT>>>(b1, b2, b3);

    zero_pk<<<(NB * 9 * 30 * 11 + 255) / 256, 256>>>();

    cudaFuncSetAttribute(poolmma, cudaFuncAttributeMaxDynamicSharedMemorySize, PM_TOT);
    poolmma<<<dim3(NB, 9, 2), 256, PM_TOT>>>(qmask, dmask);

    finish_kernel<<<dim3(NB, 9), 352>>>(qmask);
    final_kernel<<<1, 128>>>(dw, out);
}